// round 7
// baseline (speedup 1.0000x reference)
#include <cuda_runtime.h>
#include <cuda_fp16.h>
#include <cstdint>

#define MAXN 50000
#define MAXE 800000
#define H 64
#define HC 16   // H/4 float4 chunks (fp32 rows)
#define EPS 1e-5f

// ------------------------- device scratch (no allocs allowed) -------------------------
__device__ __align__(256) float  g_bufA[MAXN * H];   // layer output y (agg result, fp32)
__device__ __align__(256) __half g_hsH[MAXN * H];    // hs = (act @ W^T) * dinv, fp16
__device__ int   g_degcnt[MAXN];
__device__ int   g_rowptr[MAXN + 1];
__device__ int   g_cursor[MAXN];
__device__ int   g_csrsrc[MAXE];
__device__ float g_dinv[MAXN];
__device__ float g_sum[3 * H];     // per-layer BN stats (zeroed each replay)
__device__ float g_sumsq[3 * H];
__device__ float g_pool[64 * H];
__device__ int   g_bsum[64];

// ------------------------- utility kernels -------------------------
__global__ void zero_all_kernel(int n) {
    int i = blockIdx.x * blockDim.x + threadIdx.x;
    int stride = gridDim.x * blockDim.x;
    for (int t = i; t < n; t += stride) g_degcnt[t] = 0;
    if (i < 64 * H) g_pool[i] = 0.f;
    if (i < 3 * H) { g_sum[i] = 0.f; g_sumsq[i] = 0.f; }
}

__global__ void hist_kernel(const int* __restrict__ ei, int e) {
    int i = blockIdx.x * blockDim.x + threadIdx.x;
    int stride = gridDim.x * blockDim.x;
    for (int t = i; t < e; t += stride) {
        int dst = ei[e + t];
        atomicAdd(&g_degcnt[dst], 1);
    }
}

// block-wide inclusive scan for 1024 threads
__device__ __forceinline__ int block_incl_scan(int v, int tid) {
    __shared__ int ws[32];
    int lane = tid & 31, w = tid >> 5;
    #pragma unroll
    for (int o = 1; o < 32; o <<= 1) {
        int t = __shfl_up_sync(0xffffffffu, v, o);
        if (lane >= o) v += t;
    }
    if (lane == 31) ws[w] = v;
    __syncthreads();
    if (w == 0) {
        int s = ws[lane];
        #pragma unroll
        for (int o = 1; o < 32; o <<= 1) {
            int t = __shfl_up_sync(0xffffffffu, s, o);
            if (lane >= o) s += t;
        }
        ws[lane] = s;
    }
    __syncthreads();
    return v + (w > 0 ? ws[w - 1] : 0);
}

__global__ void scanA_kernel(int n) {
    int tid = threadIdx.x;
    int gid = blockIdx.x * 1024 + tid;
    int v = (gid < n) ? g_degcnt[gid] : 0;
    int incl = block_incl_scan(v, tid);
    if (gid < n) g_rowptr[gid] = incl - v;   // exclusive within block
    if (tid == 1023) g_bsum[blockIdx.x] = incl;   // block total
}

// scanC with fused block-offset computation (replaces scanB):
// each block sums g_bsum[0..bid-1] (<=49 values) with a 2-warp reduction.
__global__ void scanC_kernel(int n, int e, int nb) {
    __shared__ int part[2];
    __shared__ int s_off;
    int tid = threadIdx.x;
    if (tid < 64) {
        int v = (tid < blockIdx.x && tid < nb) ? g_bsum[tid] : 0;
        #pragma unroll
        for (int o = 16; o; o >>= 1) v += __shfl_xor_sync(0xffffffffu, v, o);
        if ((tid & 31) == 0) part[tid >> 5] = v;
    }
    __syncthreads();
    if (tid == 0) s_off = part[0] + part[1];
    __syncthreads();
    int off = s_off;

    int gid = blockIdx.x * 1024 + tid;
    if (gid < n) {
        int r = g_rowptr[gid] + off;
        g_rowptr[gid] = r;
        g_cursor[gid] = r;
        g_dinv[gid] = rsqrtf((float)g_degcnt[gid] + 1.0f);
    }
    if (gid == 0) g_rowptr[n] = e;
}

__global__ void fill_csr_kernel(const int* __restrict__ ei, int e) {
    int i = blockIdx.x * blockDim.x + threadIdx.x;
    int stride = gridDim.x * blockDim.x;
    for (int t = i; t < e; t += stride) {
        int s = ei[t];
        int d = ei[e + t];
        int pos = atomicAdd(&g_cursor[d], 1);
        g_csrsrc[pos] = s;
    }
}

// ------------------------- GEMM: hs = (act @ W^T) * dinv, stored fp16 ---------------------
// Block = 256 threads = 8 warps, each warp computes 4 rows x 64 cols.
// W transposed in smem (stride 65, conflict-free).
// BN: input element = relu(in*scale[k]+shift[k]); scale/shift computed inline.
template <int K, bool BN, bool FROMX>
__global__ void __launch_bounds__(256) gemm_kernel(const float* __restrict__ in,
                                                   const float* __restrict__ W,
                                                   const float* __restrict__ gamma,
                                                   const float* __restrict__ beta,
                                                   int n, int layer, float fn) {
    __shared__ float Wsm[K * 65];
    __shared__ float sScale[H], sShift[H];
    int tid = threadIdx.x;
    for (int idx = tid; idx < H * K; idx += 256) {
        int o = idx / K, k = idx - o * K;
        Wsm[k * 65 + o] = W[idx];
    }
    if (BN && tid < H) {
        float m = g_sum[layer * H + tid] / fn;
        float var = g_sumsq[layer * H + tid] / fn - m * m;
        float inv = rsqrtf(var + EPS);
        float sc = inv * gamma[tid];
        sScale[tid] = sc;
        sShift[tid] = beta[tid] - m * sc;
    }
    __syncthreads();

    const float* src = FROMX ? in : g_bufA;

    int warp = tid >> 5, lane = tid & 31;
    int row0 = (blockIdx.x * 8 + warp) * 4;

    constexpr int J = K / 32;
    float a[4][J];
    #pragma unroll
    for (int r = 0; r < 4; r++) {
        int row = row0 + r;
        #pragma unroll
        for (int j = 0; j < J; j++) {
            int k = lane + 32 * j;
            float v = 0.f;
            if (row < n) {
                v = src[(size_t)row * K + k];
                if (BN) v = fmaxf(fmaf(v, sScale[k], sShift[k]), 0.f);
            }
            a[r][j] = v;
        }
    }

    float acc[4][2];
    #pragma unroll
    for (int r = 0; r < 4; r++) { acc[r][0] = 0.f; acc[r][1] = 0.f; }

    #pragma unroll
    for (int j = 0; j < J; j++) {
        #pragma unroll
        for (int ks = 0; ks < 32; ks++) {
            int kk = j * 32 + ks;
            float w0 = Wsm[kk * 65 + lane];
            float w1 = Wsm[kk * 65 + lane + 32];
            #pragma unroll
            for (int r = 0; r < 4; r++) {
                float av = __shfl_sync(0xffffffffu, a[r][j], ks);
                acc[r][0] = fmaf(av, w0, acc[r][0]);
                acc[r][1] = fmaf(av, w1, acc[r][1]);
            }
        }
    }

    #pragma unroll
    for (int r = 0; r < 4; r++) {
        int row = row0 + r;
        if (row < n) {
            float dv = g_dinv[row];
            g_hsH[(size_t)row * H + lane]      = __float2half_rn(acc[r][0] * dv);
            g_hsH[(size_t)row * H + lane + 32] = __float2half_rn(acc[r][1] * dv);
        }
    }
}

// ------------------------- Aggregation: y = dinv*(sum_nbr hs + hs_self) + bias ------------
// R3/R6 structure; hs rows are fp16 (128B/row). Warp per node; two half-warp edge
// streams; 16 lanes x uint2 (4 halves) per row. Accumulate fp32.
__global__ void __launch_bounds__(256) agg_kernel(const float* __restrict__ bias,
                                                  int n, int layer) {
    int tid = threadIdx.x;
    int gw = (blockIdx.x * blockDim.x + tid) >> 5;
    int nw = (gridDim.x * blockDim.x) >> 5;
    int lane = tid & 31, half = lane >> 4, q = lane & 15;

    const uint2* hs2 = (const uint2*)g_hsH;   // 16 uint2 per 64-half row
    float4* out4 = (float4*)g_bufA;

    float4 s1 = make_float4(0, 0, 0, 0);
    float4 s2 = make_float4(0, 0, 0, 0);
    float4 b4 = make_float4(bias[q * 4], bias[q * 4 + 1], bias[q * 4 + 2], bias[q * 4 + 3]);

    for (int node = gw; node < n; node += nw) {
        int rs = g_rowptr[node];
        int re = g_rowptr[node + 1];
        float4 acc = make_float4(0, 0, 0, 0);
        if (half == 0) {   // self-loop term
            uint2 u = hs2[(size_t)node * 16 + q];
            float2 f0 = __half22float2(*reinterpret_cast<__half2*>(&u.x));
            float2 f1 = __half22float2(*reinterpret_cast<__half2*>(&u.y));
            acc.x = f0.x; acc.y = f0.y; acc.z = f1.x; acc.w = f1.y;
        }
        for (int e2 = rs + half; e2 < re; e2 += 2) {
            int src = g_csrsrc[e2];
            uint2 u = hs2[(size_t)src * 16 + q];
            float2 f0 = __half22float2(*reinterpret_cast<__half2*>(&u.x));
            float2 f1 = __half22float2(*reinterpret_cast<__half2*>(&u.y));
            acc.x += f0.x; acc.y += f0.y; acc.z += f1.x; acc.w += f1.y;
        }
        acc.x += __shfl_xor_sync(0xffffffffu, acc.x, 16);
        acc.y += __shfl_xor_sync(0xffffffffu, acc.y, 16);
        acc.z += __shfl_xor_sync(0xffffffffu, acc.z, 16);
        acc.w += __shfl_xor_sync(0xffffffffu, acc.w, 16);
        if (half == 0) {
            float dv = g_dinv[node];
            float4 y;
            y.x = fmaf(acc.x, dv, b4.x);
            y.y = fmaf(acc.y, dv, b4.y);
            y.z = fmaf(acc.z, dv, b4.z);
            y.w = fmaf(acc.w, dv, b4.w);
            out4[(size_t)node * HC + q] = y;
            s1.x += y.x; s1.y += y.y; s1.z += y.z; s1.w += y.w;
            s2.x += y.x * y.x; s2.y += y.y * y.y; s2.z += y.z * y.z; s2.w += y.w * y.w;
        }
    }

    __shared__ float ssum[H], ssq[H];
    if (tid < H) { ssum[tid] = 0.f; ssq[tid] = 0.f; }
    __syncthreads();
    if (half == 0) {
        int c0 = q * 4;
        atomicAdd(&ssum[c0 + 0], s1.x); atomicAdd(&ssum[c0 + 1], s1.y);
        atomicAdd(&ssum[c0 + 2], s1.z); atomicAdd(&ssum[c0 + 3], s1.w);
        atomicAdd(&ssq[c0 + 0], s2.x);  atomicAdd(&ssq[c0 + 1], s2.y);
        atomicAdd(&ssq[c0 + 2], s2.z);  atomicAdd(&ssq[c0 + 3], s2.w);
    }
    __syncthreads();
    if (tid < H) {
        atomicAdd(&g_sum[layer * H + tid], ssum[tid]);
        atomicAdd(&g_sumsq[layer * H + tid], ssq[tid]);
    }
}

// ------------------------- pooling: segment mean over sorted batch -------------------------
__global__ void __launch_bounds__(256) pool_kernel(const int* __restrict__ batch,
                                                   const float* __restrict__ gamma,
                                                   const float* __restrict__ beta,
                                                   int n, float fn) {
    __shared__ float sScale[H], sShift[H];
    int tid = threadIdx.x;
    if (tid < H) {
        float m = g_sum[2 * H + tid] / fn;
        float var = g_sumsq[2 * H + tid] / fn - m * m;
        float inv = rsqrtf(var + EPS);
        float sc = inv * gamma[tid];
        sScale[tid] = sc;
        sShift[tid] = beta[tid] - m * sc;
    }
    __syncthreads();

    int g = blockIdx.x >> 3, sub = blockIdx.x & 7;
    int start, end;
    {
        int key = g;
        int lo = 0, hi = n;
        while (lo < hi) { int mid = (lo + hi) >> 1; if (batch[mid] < key) lo = mid + 1; else hi = mid; }
        start = lo;
        key = g + 1;
        lo = 0; hi = n;
        while (lo < hi) { int mid = (lo + hi) >> 1; if (batch[mid] < key) lo = mid + 1; else hi = mid; }
        end = lo;
    }
    int c = tid & 63;
    int rr = tid >> 6;  // 0..3
    float sc = sScale[c], sh = sShift[c];
    float cnt = fmaxf((float)(end - start), 1.f);
    float s = 0.f;
    for (int row = start + sub * 4 + rr; row < end; row += 32)
        s += fmaxf(fmaf(g_bufA[(size_t)row * H + c], sc, sh), 0.f);

    __shared__ float sm[256];
    sm[tid] = s;
    __syncthreads();
    if (tid < 128) sm[tid] += sm[tid + 128];
    __syncthreads();
    if (tid < 64) atomicAdd(&g_pool[g * H + tid], (sm[tid] + sm[tid + 64]) / cnt);
}

// ------------------------- final MLP -------------------------
__global__ void mlp_kernel(const float* __restrict__ l1w, const float* __restrict__ l1b,
                           const float* __restrict__ l2w, const float* __restrict__ l2b,
                           float* __restrict__ out) {
    int g = blockIdx.x, j = threadIdx.x;  // 32 threads
    __shared__ float p[H];
    p[j]      = g_pool[g * H + j];
    p[j + 32] = g_pool[g * H + j + 32];
    __syncwarp();
    float h = l1b[j];
    #pragma unroll
    for (int k = 0; k < H; k++) h = fmaf(p[k], l1w[j * H + k], h);
    h = fmaxf(h, 0.f);
    float v = h * l2w[j];
    #pragma unroll
    for (int o = 16; o; o >>= 1) v += __shfl_xor_sync(0xffffffffu, v, o);
    if (j == 0) out[g] = v + l2b[0];
}

// ------------------------- host launcher -------------------------
extern "C" void kernel_launch(void* const* d_in, const int* in_sizes, int n_in,
                              void* d_out, int out_size) {
    const float* x     = (const float*)d_in[0];
    const int*   ei    = (const int*)d_in[1];     // int32 on device (JAX x64 disabled)
    const int*   batch = (const int*)d_in[2];
    const float* W0  = (const float*)d_in[3];
    const float* b0  = (const float*)d_in[4];
    const float* gm0 = (const float*)d_in[5];
    const float* be0 = (const float*)d_in[6];
    const float* W1  = (const float*)d_in[7];
    const float* b1  = (const float*)d_in[8];
    const float* gm1 = (const float*)d_in[9];
    const float* be1 = (const float*)d_in[10];
    const float* W2  = (const float*)d_in[11];
    const float* b2  = (const float*)d_in[12];
    const float* gm2 = (const float*)d_in[13];
    const float* be2 = (const float*)d_in[14];
    const float* l1w = (const float*)d_in[15];
    const float* l1b = (const float*)d_in[16];
    const float* l2w = (const float*)d_in[17];
    const float* l2b = (const float*)d_in[18];

    int n = in_sizes[0] / 128;     // nodes
    int e = in_sizes[1] / 2;       // edges
    int G = out_size;              // graphs (64)

    // CSR build (coalesced scan; scanB folded into scanC)
    zero_all_kernel<<<(n + 255) / 256, 256>>>(n);
    hist_kernel<<<(e + 255) / 256, 256>>>(ei, e);
    int nb = (n + 1023) / 1024;
    scanA_kernel<<<nb, 1024>>>(n);
    scanC_kernel<<<nb, 1024>>>(n, e, nb);
    fill_csr_kernel<<<(e + 255) / 256, 256>>>(ei, e);

    int gemm_grid = (n + 31) / 32;
    float fn = (float)n;

    // Layer 0
    gemm_kernel<128, false, true><<<gemm_grid, 256>>>(x, W0, nullptr, nullptr, n, 0, fn);
    agg_kernel<<<512, 256>>>(b0, n, 0);
    // Layer 1 (BN of layer-0 stats applied inline)
    gemm_kernel<64, true, false><<<gemm_grid, 256>>>(nullptr, W1, gm0, be0, n, 0, fn);
    agg_kernel<<<512, 256>>>(b1, n, 1);
    // Layer 2
    gemm_kernel<64, true, false><<<gemm_grid, 256>>>(nullptr, W2, gm1, be1, n, 1, fn);
    agg_kernel<<<512, 256>>>(b2, n, 2);

    // Pool (BN of layer-2 stats inline) + MLP
    pool_kernel<<<G * 8, 256>>>(batch, gm2, be2, n, fn);
    mlp_kernel<<<G, 32>>>(l1w, l1b, l2w, l2b, (float*)d_out);
}

// round 8
// speedup vs baseline: 1.0182x; 1.0182x over previous
#include <cuda_runtime.h>
#include <cuda_bf16.h>
#include <cstdint>

#define MAXN 50000
#define MAXE 800000
#define H 64
#define HC 16   // H/4 float4 chunks
#define EPS 1e-5f

// ------------------------- device scratch (no allocs allowed) -------------------------
// Zero-state invariant: g_degcnt, g_pool, g_sum, g_sumsq are zero at entry of every
// kernel_launch call (zero-initialized at module load; each replay restores them).
__device__ __align__(256) float g_bufA[MAXN * H];   // layer output y (agg result)
__device__ __align__(256) float g_bufB[MAXN * H];   // hs = (act @ W^T) * dinv
__device__ int   g_degcnt[MAXN];
__device__ int   g_rowptr[MAXN + 1];
__device__ int   g_cursor[MAXN];
__device__ int   g_csrsrc[MAXE];
__device__ float g_dinv[MAXN];
__device__ float g_sum[3 * H];     // per-layer BN stats
__device__ float g_sumsq[3 * H];
__device__ float g_pool[64 * H];
__device__ int   g_bsum[64];

// ------------------------- CSR build -------------------------
__global__ void hist_kernel(const int* __restrict__ ei, int e) {
    int i = blockIdx.x * blockDim.x + threadIdx.x;
    int stride = gridDim.x * blockDim.x;
    for (int t = i; t < e; t += stride) {
        int dst = ei[e + t];
        atomicAdd(&g_degcnt[dst], 1);
    }
}

// block-wide inclusive scan for 1024 threads
__device__ __forceinline__ int block_incl_scan(int v, int tid) {
    __shared__ int ws[32];
    int lane = tid & 31, w = tid >> 5;
    #pragma unroll
    for (int o = 1; o < 32; o <<= 1) {
        int t = __shfl_up_sync(0xffffffffu, v, o);
        if (lane >= o) v += t;
    }
    if (lane == 31) ws[w] = v;
    __syncthreads();
    if (w == 0) {
        int s = ws[lane];
        #pragma unroll
        for (int o = 1; o < 32; o <<= 1) {
            int t = __shfl_up_sync(0xffffffffu, s, o);
            if (lane >= o) s += t;
        }
        ws[lane] = s;
    }
    __syncthreads();
    return v + (w > 0 ? ws[w - 1] : 0);
}

__global__ void scanA_kernel(int n) {
    int tid = threadIdx.x;
    int gid = blockIdx.x * 1024 + tid;
    int v = (gid < n) ? g_degcnt[gid] : 0;
    int incl = block_incl_scan(v, tid);
    if (gid < n) g_rowptr[gid] = incl - v;   // exclusive within block
    if (tid == 1023) g_bsum[blockIdx.x] = incl;   // block total
}

// scanC: adds block offsets (sums g_bsum[0..bid-1], <=64 values, 2-warp reduction),
// writes rowptr/cursor/dinv, and RESTORES g_degcnt to zero for the next replay.
__global__ void scanC_kernel(int n, int e, int nb) {
    __shared__ int part[2];
    __shared__ int s_off;
    int tid = threadIdx.x;
    if (tid < 64) {
        int v = (tid < blockIdx.x && tid < nb) ? g_bsum[tid] : 0;
        #pragma unroll
        for (int o = 16; o; o >>= 1) v += __shfl_xor_sync(0xffffffffu, v, o);
        if ((tid & 31) == 0) part[tid >> 5] = v;
    }
    __syncthreads();
    if (tid == 0) s_off = part[0] + part[1];
    __syncthreads();
    int off = s_off;

    int gid = blockIdx.x * 1024 + tid;
    if (gid < n) {
        int d = g_degcnt[gid];
        int r = g_rowptr[gid] + off;
        g_rowptr[gid] = r;
        g_cursor[gid] = r;
        g_dinv[gid] = rsqrtf((float)d + 1.0f);
        g_degcnt[gid] = 0;      // restore zero invariant
    }
    if (gid == 0) g_rowptr[n] = e;
}

__global__ void fill_csr_kernel(const int* __restrict__ ei, int e) {
    int i = blockIdx.x * blockDim.x + threadIdx.x;
    int stride = gridDim.x * blockDim.x;
    for (int t = i; t < e; t += stride) {
        int s = ei[t];
        int d = ei[e + t];
        int pos = atomicAdd(&g_cursor[d], 1);
        g_csrsrc[pos] = s;
    }
}

// ------------------------- GEMM: hs = (act @ W^T) * dinv -------------------------
// Block = 256 threads = 8 warps, each warp computes 4 rows x 64 cols.
// W transposed in smem (stride 65, conflict-free).
// BN: input element = relu(in*scale[k]+shift[k]); scale/shift computed inline.
template <int K, bool BN, bool FROMX>
__global__ void __launch_bounds__(256) gemm_kernel(const float* __restrict__ in,
                                                   const float* __restrict__ W,
                                                   const float* __restrict__ gamma,
                                                   const float* __restrict__ beta,
                                                   int n, int layer, float fn) {
    __shared__ float Wsm[K * 65];
    __shared__ float sScale[H], sShift[H];
    int tid = threadIdx.x;
    for (int idx = tid; idx < H * K; idx += 256) {
        int o = idx / K, k = idx - o * K;
        Wsm[k * 65 + o] = W[idx];
    }
    if (BN && tid < H) {
        float m = g_sum[layer * H + tid] / fn;
        float var = g_sumsq[layer * H + tid] / fn - m * m;
        float inv = rsqrtf(var + EPS);
        float sc = inv * gamma[tid];
        sScale[tid] = sc;
        sShift[tid] = beta[tid] - m * sc;
    }
    __syncthreads();

    const float* src = FROMX ? in : g_bufA;

    int warp = tid >> 5, lane = tid & 31;
    int row0 = (blockIdx.x * 8 + warp) * 4;

    constexpr int J = K / 32;
    float a[4][J];
    #pragma unroll
    for (int r = 0; r < 4; r++) {
        int row = row0 + r;
        #pragma unroll
        for (int j = 0; j < J; j++) {
            int k = lane + 32 * j;
            float v = 0.f;
            if (row < n) {
                v = src[(size_t)row * K + k];
                if (BN) v = fmaxf(fmaf(v, sScale[k], sShift[k]), 0.f);
            }
            a[r][j] = v;
        }
    }

    float acc[4][2];
    #pragma unroll
    for (int r = 0; r < 4; r++) { acc[r][0] = 0.f; acc[r][1] = 0.f; }

    #pragma unroll
    for (int j = 0; j < J; j++) {
        #pragma unroll
        for (int ks = 0; ks < 32; ks++) {
            int kk = j * 32 + ks;
            float w0 = Wsm[kk * 65 + lane];
            float w1 = Wsm[kk * 65 + lane + 32];
            #pragma unroll
            for (int r = 0; r < 4; r++) {
                float av = __shfl_sync(0xffffffffu, a[r][j], ks);
                acc[r][0] = fmaf(av, w0, acc[r][0]);
                acc[r][1] = fmaf(av, w1, acc[r][1]);
            }
        }
    }

    #pragma unroll
    for (int r = 0; r < 4; r++) {
        int row = row0 + r;
        if (row < n) {
            float dv = g_dinv[row];
            g_bufB[(size_t)row * H + lane]      = acc[r][0] * dv;
            g_bufB[(size_t)row * H + lane + 32] = acc[r][1] * dv;
        }
    }
}

// ------------------------- Aggregation: y = dinv*(sum_nbr hs + hs_self) + bias ------------
// Proven 2-stream structure (R3/R6); warp per node; 16 lanes x float4.
__global__ void __launch_bounds__(256) agg_kernel(const float* __restrict__ bias,
                                                  int n, int layer) {
    int tid = threadIdx.x;
    int gw = (blockIdx.x * blockDim.x + tid) >> 5;
    int nw = (gridDim.x * blockDim.x) >> 5;
    int lane = tid & 31, half = lane >> 4, q = lane & 15;

    const float4* hs4 = (const float4*)g_bufB;
    float4* out4 = (float4*)g_bufA;

    float4 s1 = make_float4(0, 0, 0, 0);
    float4 s2 = make_float4(0, 0, 0, 0);
    float4 b4 = make_float4(bias[q * 4], bias[q * 4 + 1], bias[q * 4 + 2], bias[q * 4 + 3]);

    for (int node = gw; node < n; node += nw) {
        int rs = g_rowptr[node];
        int re = g_rowptr[node + 1];
        float4 acc;
        if (half == 0) acc = hs4[(size_t)node * HC + q];   // self-loop term
        else           acc = make_float4(0, 0, 0, 0);
        for (int e2 = rs + half; e2 < re; e2 += 2) {
            int src = g_csrsrc[e2];
            float4 v = hs4[(size_t)src * HC + q];
            acc.x += v.x; acc.y += v.y; acc.z += v.z; acc.w += v.w;
        }
        acc.x += __shfl_xor_sync(0xffffffffu, acc.x, 16);
        acc.y += __shfl_xor_sync(0xffffffffu, acc.y, 16);
        acc.z += __shfl_xor_sync(0xffffffffu, acc.z, 16);
        acc.w += __shfl_xor_sync(0xffffffffu, acc.w, 16);
        if (half == 0) {
            float dv = g_dinv[node];
            float4 y;
            y.x = fmaf(acc.x, dv, b4.x);
            y.y = fmaf(acc.y, dv, b4.y);
            y.z = fmaf(acc.z, dv, b4.z);
            y.w = fmaf(acc.w, dv, b4.w);
            out4[(size_t)node * HC + q] = y;
            s1.x += y.x; s1.y += y.y; s1.z += y.z; s1.w += y.w;
            s2.x += y.x * y.x; s2.y += y.y * y.y; s2.z += y.z * y.z; s2.w += y.w * y.w;
        }
    }

    __shared__ float ssum[H], ssq[H];
    if (tid < H) { ssum[tid] = 0.f; ssq[tid] = 0.f; }
    __syncthreads();
    if (half == 0) {
        int c0 = q * 4;
        atomicAdd(&ssum[c0 + 0], s1.x); atomicAdd(&ssum[c0 + 1], s1.y);
        atomicAdd(&ssum[c0 + 2], s1.z); atomicAdd(&ssum[c0 + 3], s1.w);
        atomicAdd(&ssq[c0 + 0], s2.x);  atomicAdd(&ssq[c0 + 1], s2.y);
        atomicAdd(&ssq[c0 + 2], s2.z);  atomicAdd(&ssq[c0 + 3], s2.w);
    }
    __syncthreads();
    if (tid < H) {
        atomicAdd(&g_sum[layer * H + tid], ssum[tid]);
        atomicAdd(&g_sumsq[layer * H + tid], ssq[tid]);
    }
}

// ------------------------- pooling: segment mean over sorted batch -------------------------
__global__ void __launch_bounds__(256) pool_kernel(const int* __restrict__ batch,
                                                   const float* __restrict__ gamma,
                                                   const float* __restrict__ beta,
                                                   int n, float fn) {
    __shared__ float sScale[H], sShift[H];
    int tid = threadIdx.x;
    if (tid < H) {
        float m = g_sum[2 * H + tid] / fn;
        float var = g_sumsq[2 * H + tid] / fn - m * m;
        float inv = rsqrtf(var + EPS);
        float sc = inv * gamma[tid];
        sScale[tid] = sc;
        sShift[tid] = beta[tid] - m * sc;
    }
    __syncthreads();

    int g = blockIdx.x >> 3, sub = blockIdx.x & 7;
    int start, end;
    {
        int key = g;
        int lo = 0, hi = n;
        while (lo < hi) { int mid = (lo + hi) >> 1; if (batch[mid] < key) lo = mid + 1; else hi = mid; }
        start = lo;
        key = g + 1;
        lo = 0; hi = n;
        while (lo < hi) { int mid = (lo + hi) >> 1; if (batch[mid] < key) lo = mid + 1; else hi = mid; }
        end = lo;
    }
    int c = tid & 63;
    int rr = tid >> 6;  // 0..3
    float sc = sScale[c], sh = sShift[c];
    float cnt = fmaxf((float)(end - start), 1.f);
    float s = 0.f;
    for (int row = start + sub * 4 + rr; row < end; row += 32)
        s += fmaxf(fmaf(g_bufA[(size_t)row * H + c], sc, sh), 0.f);

    __shared__ float sm[256];
    sm[tid] = s;
    __syncthreads();
    if (tid < 128) sm[tid] += sm[tid + 128];
    __syncthreads();
    if (tid < 64) atomicAdd(&g_pool[g * H + tid], (sm[tid] + sm[tid + 64]) / cnt);
}

// ------------------------- final MLP (also restores zero invariants) ----------------------
__global__ void mlp_kernel(const float* __restrict__ l1w, const float* __restrict__ l1b,
                           const float* __restrict__ l2w, const float* __restrict__ l2b,
                           float* __restrict__ out) {
    int g = blockIdx.x, j = threadIdx.x;  // 32 threads
    __shared__ float p[H];
    p[j]      = g_pool[g * H + j];
    p[j + 32] = g_pool[g * H + j + 32];
    // restore zero invariant for next replay
    g_pool[g * H + j] = 0.f;
    g_pool[g * H + j + 32] = 0.f;
    if (g == 0) {
        for (int t = j; t < 3 * H; t += 32) { g_sum[t] = 0.f; g_sumsq[t] = 0.f; }
    }
    __syncwarp();
    float h = l1b[j];
    #pragma unroll
    for (int k = 0; k < H; k++) h = fmaf(p[k], l1w[j * H + k], h);
    h = fmaxf(h, 0.f);
    float v = h * l2w[j];
    #pragma unroll
    for (int o = 16; o; o >>= 1) v += __shfl_xor_sync(0xffffffffu, v, o);
    if (j == 0) out[g] = v + l2b[0];
}

// ------------------------- host launcher -------------------------
extern "C" void kernel_launch(void* const* d_in, const int* in_sizes, int n_in,
                              void* d_out, int out_size) {
    const float* x     = (const float*)d_in[0];
    const int*   ei    = (const int*)d_in[1];     // int32 on device (JAX x64 disabled)
    const int*   batch = (const int*)d_in[2];
    const float* W0  = (const float*)d_in[3];
    const float* b0  = (const float*)d_in[4];
    const float* gm0 = (const float*)d_in[5];
    const float* be0 = (const float*)d_in[6];
    const float* W1  = (const float*)d_in[7];
    const float* b1  = (const float*)d_in[8];
    const float* gm1 = (const float*)d_in[9];
    const float* be1 = (const float*)d_in[10];
    const float* W2  = (const float*)d_in[11];
    const float* b2  = (const float*)d_in[12];
    const float* gm2 = (const float*)d_in[13];
    const float* be2 = (const float*)d_in[14];
    const float* l1w = (const float*)d_in[15];
    const float* l1b = (const float*)d_in[16];
    const float* l2w = (const float*)d_in[17];
    const float* l2b = (const float*)d_in[18];

    int n = in_sizes[0] / 128;     // nodes
    int e = in_sizes[1] / 2;       // edges
    int G = out_size;              // graphs (64)

    int nb = (n + 1023) / 1024;
    int gemm_grid = (n + 31) / 32;
    float fn = (float)n;

    // CSR build; gemm0 hoisted before fill_csr (only needs dinv) so launch #4 = gemm0
    hist_kernel<<<(e + 255) / 256, 256>>>(ei, e);                                      // 1
    scanA_kernel<<<nb, 1024>>>(n);                                                     // 2
    scanC_kernel<<<nb, 1024>>>(n, e, nb);                                              // 3
    gemm_kernel<128, false, true><<<gemm_grid, 256>>>(x, W0, nullptr, nullptr, n, 0, fn); // 4
    fill_csr_kernel<<<(e + 255) / 256, 256>>>(ei, e);                                  // 5

    // Layer 0 aggregation
    agg_kernel<<<1024, 256>>>(b0, n, 0);                                               // 6
    // Layer 1
    gemm_kernel<64, true, false><<<gemm_grid, 256>>>(nullptr, W1, gm0, be0, n, 0, fn); // 7
    agg_kernel<<<1024, 256>>>(b1, n, 1);                                               // 8
    // Layer 2
    gemm_kernel<64, true, false><<<gemm_grid, 256>>>(nullptr, W2, gm1, be1, n, 1, fn); // 9
    agg_kernel<<<1024, 256>>>(b2, n, 2);                                               // 10

    // Pool + MLP
    pool_kernel<<<G * 8, 256>>>(batch, gm2, be2, n, fn);                               // 11
    mlp_kernel<<<G, 32>>>(l1w, l1b, l2w, l2b, (float*)d_out);                          // 12
}

// round 9
// speedup vs baseline: 1.0895x; 1.0700x over previous
#include <cuda_runtime.h>
#include <cuda_bf16.h>
#include <cstdint>

#define MAXN 50000
#define MAXE 800000
#define H 64
#define HC 16   // H/4 float4 chunks
#define EPS 1e-5f

// ------------------------- device scratch (no allocs allowed) -------------------------
// Zero-state invariant: g_degcnt, g_pool, g_sum, g_sumsq are zero at entry of every
// kernel_launch call (zero-initialized at module load; each replay restores them).
__device__ __align__(256) float g_bufA[MAXN * H];   // layer output y (agg result)
__device__ __align__(256) float g_bufB[MAXN * H];   // hs = (act @ W^T) * dinv
__device__ int   g_degcnt[MAXN];
__device__ int   g_rowptr[MAXN + 1];
__device__ int   g_cursor[MAXN];
__device__ int   g_csrsrc[MAXE];
__device__ float g_dinv[MAXN];
__device__ float g_sum[3 * H];     // per-layer BN stats
__device__ float g_sumsq[3 * H];
__device__ float g_pool[64 * H];
__device__ int   g_bsum[64];

// ------------------------- CSR build -------------------------
__global__ void hist_kernel(const int* __restrict__ ei, int e) {
    int i = blockIdx.x * blockDim.x + threadIdx.x;
    int stride = gridDim.x * blockDim.x;
    for (int t = i; t < e; t += stride) {
        int dst = ei[e + t];
        atomicAdd(&g_degcnt[dst], 1);
    }
}

__device__ __forceinline__ int block_incl_scan(int v, int tid) {
    __shared__ int ws[32];
    int lane = tid & 31, w = tid >> 5;
    #pragma unroll
    for (int o = 1; o < 32; o <<= 1) {
        int t = __shfl_up_sync(0xffffffffu, v, o);
        if (lane >= o) v += t;
    }
    if (lane == 31) ws[w] = v;
    __syncthreads();
    if (w == 0) {
        int s = ws[lane];
        #pragma unroll
        for (int o = 1; o < 32; o <<= 1) {
            int t = __shfl_up_sync(0xffffffffu, s, o);
            if (lane >= o) s += t;
        }
        ws[lane] = s;
    }
    __syncthreads();
    return v + (w > 0 ? ws[w - 1] : 0);
}

__global__ void scanA_kernel(int n) {
    int tid = threadIdx.x;
    int gid = blockIdx.x * 1024 + tid;
    int v = (gid < n) ? g_degcnt[gid] : 0;
    int incl = block_incl_scan(v, tid);
    if (gid < n) g_rowptr[gid] = incl - v;
    if (tid == 1023) g_bsum[blockIdx.x] = incl;
}

// scanC: adds block offsets, writes rowptr/cursor/dinv, restores g_degcnt to zero.
__global__ void scanC_kernel(int n, int e, int nb) {
    __shared__ int part[2];
    __shared__ int s_off;
    int tid = threadIdx.x;
    if (tid < 64) {
        int v = (tid < blockIdx.x && tid < nb) ? g_bsum[tid] : 0;
        #pragma unroll
        for (int o = 16; o; o >>= 1) v += __shfl_xor_sync(0xffffffffu, v, o);
        if ((tid & 31) == 0) part[tid >> 5] = v;
    }
    __syncthreads();
    if (tid == 0) s_off = part[0] + part[1];
    __syncthreads();
    int off = s_off;

    int gid = blockIdx.x * 1024 + tid;
    if (gid < n) {
        int d = g_degcnt[gid];
        int r = g_rowptr[gid] + off;
        g_rowptr[gid] = r;
        g_cursor[gid] = r;
        g_dinv[gid] = rsqrtf((float)d + 1.0f);
        g_degcnt[gid] = 0;
    }
    if (gid == 0) g_rowptr[n] = e;
}

__global__ void fill_csr_kernel(const int* __restrict__ ei, int e) {
    int i = blockIdx.x * blockDim.x + threadIdx.x;
    int stride = gridDim.x * blockDim.x;
    for (int t = i; t < e; t += stride) {
        int s = ei[t];
        int d = ei[e + t];
        int pos = atomicAdd(&g_cursor[d], 1);
        g_csrsrc[pos] = s;
    }
}

// ------------------------- GEMM: hs = (act @ W^T) * dinv -------------------------
// Register-tiled, shuffle-free. Block = 256 threads = 64 rows x 64 cols tile;
// each thread computes 4x4. A staged TRANSPOSED in smem (a_sm[k][row]), W as
// w_sm[k][col], in 64-wide K chunks. Inner loop: 2 LDS.128 + 16 FFMA per k.
// BN+ReLU folded into the A-stage; dinv at store.
#define KT 64          // K chunk
#define SMS 68         // smem row stride (floats), multiple of 4, conflict-free
template <int K, bool BN, bool FROMX>
__global__ void __launch_bounds__(256) gemm_kernel(const float* __restrict__ in,
                                                   const float* __restrict__ W,
                                                   const float* __restrict__ gamma,
                                                   const float* __restrict__ beta,
                                                   int n, int layer, float fn) {
    __shared__ float a_sm[KT * SMS];
    __shared__ float w_sm[KT * SMS];
    __shared__ float sScale[H], sShift[H];

    int tid = threadIdx.x;
    int row0 = blockIdx.x * 64;

    if (BN) {
        if (tid < H) {
            float m = g_sum[layer * H + tid] / fn;
            float var = g_sumsq[layer * H + tid] / fn - m * m;
            float inv = rsqrtf(var + EPS);
            float sc = inv * gamma[tid];
            sScale[tid] = sc;
            sShift[tid] = beta[tid] - m * sc;
        }
        __syncthreads();
    }

    const float* src = FROMX ? in : g_bufA;

    int tx = tid & 15;          // output col group: cols tx*4 .. tx*4+3
    int ty = tid >> 4;          // output row group: rows ty*4 .. ty*4+3

    float acc[4][4];
    #pragma unroll
    for (int r = 0; r < 4; r++)
        #pragma unroll
        for (int c = 0; c < 4; c++) acc[r][c] = 0.f;

    #pragma unroll
    for (int kt = 0; kt < K; kt += KT) {
        // stage W chunk: w_sm[k][o]
        #pragma unroll
        for (int it = 0; it < 4; it++) {
            int idx = it * 256 + tid;            // float4 index
            int o = idx & 63;
            int kc = (idx >> 6) << 2;            // 0..60
            float4 wv = *(const float4*)&W[o * K + kt + kc];
            w_sm[(kc + 0) * SMS + o] = wv.x;
            w_sm[(kc + 1) * SMS + o] = wv.y;
            w_sm[(kc + 2) * SMS + o] = wv.z;
            w_sm[(kc + 3) * SMS + o] = wv.w;
        }
        // stage A chunk transposed: a_sm[k][row], BN+ReLU applied
        #pragma unroll
        for (int it = 0; it < 4; it++) {
            int idx = it * 256 + tid;
            int row = idx & 63;
            int kc = (idx >> 6) << 2;
            int rg = row0 + row;
            float4 av = make_float4(0.f, 0.f, 0.f, 0.f);
            if (rg < n) {
                av = *(const float4*)&src[(size_t)rg * K + kt + kc];
                if (BN) {
                    float4 sc4 = *(const float4*)&sScale[kt + kc];
                    float4 sh4 = *(const float4*)&sShift[kt + kc];
                    av.x = fmaxf(fmaf(av.x, sc4.x, sh4.x), 0.f);
                    av.y = fmaxf(fmaf(av.y, sc4.y, sh4.y), 0.f);
                    av.z = fmaxf(fmaf(av.z, sc4.z, sh4.z), 0.f);
                    av.w = fmaxf(fmaf(av.w, sc4.w, sh4.w), 0.f);
                }
            }
            a_sm[(kc + 0) * SMS + row] = av.x;
            a_sm[(kc + 1) * SMS + row] = av.y;
            a_sm[(kc + 2) * SMS + row] = av.z;
            a_sm[(kc + 3) * SMS + row] = av.w;
        }
        __syncthreads();

        #pragma unroll 8
        for (int k = 0; k < KT; k++) {
            float4 a4 = *(const float4*)&a_sm[k * SMS + ty * 4];
            float4 b4 = *(const float4*)&w_sm[k * SMS + tx * 4];
            float ar[4] = {a4.x, a4.y, a4.z, a4.w};
            float br[4] = {b4.x, b4.y, b4.z, b4.w};
            #pragma unroll
            for (int r = 0; r < 4; r++)
                #pragma unroll
                for (int c = 0; c < 4; c++)
                    acc[r][c] = fmaf(ar[r], br[c], acc[r][c]);
        }
        __syncthreads();
    }

    #pragma unroll
    for (int r = 0; r < 4; r++) {
        int rg = row0 + ty * 4 + r;
        if (rg < n) {
            float dv = g_dinv[rg];
            float4 o4 = make_float4(acc[r][0] * dv, acc[r][1] * dv,
                                    acc[r][2] * dv, acc[r][3] * dv);
            *(float4*)&g_bufB[(size_t)rg * H + tx * 4] = o4;
        }
    }
}

// ------------------------- Aggregation: y = dinv*(sum_nbr hs + hs_self) + bias ------------
// Proven 2-stream structure; warp per node; 16 lanes x float4.
__global__ void __launch_bounds__(256) agg_kernel(const float* __restrict__ bias,
                                                  int n, int layer) {
    int tid = threadIdx.x;
    int gw = (blockIdx.x * blockDim.x + tid) >> 5;
    int nw = (gridDim.x * blockDim.x) >> 5;
    int lane = tid & 31, half = lane >> 4, q = lane & 15;

    const float4* hs4 = (const float4*)g_bufB;
    float4* out4 = (float4*)g_bufA;

    float4 s1 = make_float4(0, 0, 0, 0);
    float4 s2 = make_float4(0, 0, 0, 0);
    float4 b4 = make_float4(bias[q * 4], bias[q * 4 + 1], bias[q * 4 + 2], bias[q * 4 + 3]);

    for (int node = gw; node < n; node += nw) {
        int rs = g_rowptr[node];
        int re = g_rowptr[node + 1];
        float4 acc;
        if (half == 0) acc = hs4[(size_t)node * HC + q];   // self-loop term
        else           acc = make_float4(0, 0, 0, 0);
        for (int e2 = rs + half; e2 < re; e2 += 2) {
            int src = g_csrsrc[e2];
            float4 v = hs4[(size_t)src * HC + q];
            acc.x += v.x; acc.y += v.y; acc.z += v.z; acc.w += v.w;
        }
        acc.x += __shfl_xor_sync(0xffffffffu, acc.x, 16);
        acc.y += __shfl_xor_sync(0xffffffffu, acc.y, 16);
        acc.z += __shfl_xor_sync(0xffffffffu, acc.z, 16);
        acc.w += __shfl_xor_sync(0xffffffffu, acc.w, 16);
        if (half == 0) {
            float dv = g_dinv[node];
            float4 y;
            y.x = fmaf(acc.x, dv, b4.x);
            y.y = fmaf(acc.y, dv, b4.y);
            y.z = fmaf(acc.z, dv, b4.z);
            y.w = fmaf(acc.w, dv, b4.w);
            out4[(size_t)node * HC + q] = y;
            s1.x += y.x; s1.y += y.y; s1.z += y.z; s1.w += y.w;
            s2.x += y.x * y.x; s2.y += y.y * y.y; s2.z += y.z * y.z; s2.w += y.w * y.w;
        }
    }

    __shared__ float ssum[H], ssq[H];
    if (tid < H) { ssum[tid] = 0.f; ssq[tid] = 0.f; }
    __syncthreads();
    if (half == 0) {
        int c0 = q * 4;
        atomicAdd(&ssum[c0 + 0], s1.x); atomicAdd(&ssum[c0 + 1], s1.y);
        atomicAdd(&ssum[c0 + 2], s1.z); atomicAdd(&ssum[c0 + 3], s1.w);
        atomicAdd(&ssq[c0 + 0], s2.x);  atomicAdd(&ssq[c0 + 1], s2.y);
        atomicAdd(&ssq[c0 + 2], s2.z);  atomicAdd(&ssq[c0 + 3], s2.w);
    }
    __syncthreads();
    if (tid < H) {
        atomicAdd(&g_sum[layer * H + tid], ssum[tid]);
        atomicAdd(&g_sumsq[layer * H + tid], ssq[tid]);
    }
}

// ------------------------- pooling: segment mean over sorted batch -------------------------
__global__ void __launch_bounds__(256) pool_kernel(const int* __restrict__ batch,
                                                   const float* __restrict__ gamma,
                                                   const float* __restrict__ beta,
                                                   int n, float fn) {
    __shared__ float sScale[H], sShift[H];
    int tid = threadIdx.x;
    if (tid < H) {
        float m = g_sum[2 * H + tid] / fn;
        float var = g_sumsq[2 * H + tid] / fn - m * m;
        float inv = rsqrtf(var + EPS);
        float sc = inv * gamma[tid];
        sScale[tid] = sc;
        sShift[tid] = beta[tid] - m * sc;
    }
    __syncthreads();

    int g = blockIdx.x >> 3, sub = blockIdx.x & 7;
    int start, end;
    {
        int key = g;
        int lo = 0, hi = n;
        while (lo < hi) { int mid = (lo + hi) >> 1; if (batch[mid] < key) lo = mid + 1; else hi = mid; }
        start = lo;
        key = g + 1;
        lo = 0; hi = n;
        while (lo < hi) { int mid = (lo + hi) >> 1; if (batch[mid] < key) lo = mid + 1; else hi = mid; }
        end = lo;
    }
    int c = tid & 63;
    int rr = tid >> 6;  // 0..3
    float sc = sScale[c], sh = sShift[c];
    float cnt = fmaxf((float)(end - start), 1.f);
    float s = 0.f;
    for (int row = start + sub * 4 + rr; row < end; row += 32)
        s += fmaxf(fmaf(g_bufA[(size_t)row * H + c], sc, sh), 0.f);

    __shared__ float sm[256];
    sm[tid] = s;
    __syncthreads();
    if (tid < 128) sm[tid] += sm[tid + 128];
    __syncthreads();
    if (tid < 64) atomicAdd(&g_pool[g * H + tid], (sm[tid] + sm[tid + 64]) / cnt);
}

// ------------------------- final MLP (also restores zero invariants) ----------------------
__global__ void mlp_kernel(const float* __restrict__ l1w, const float* __restrict__ l1b,
                           const float* __restrict__ l2w, const float* __restrict__ l2b,
                           float* __restrict__ out) {
    int g = blockIdx.x, j = threadIdx.x;  // 32 threads
    __shared__ float p[H];
    p[j]      = g_pool[g * H + j];
    p[j + 32] = g_pool[g * H + j + 32];
    g_pool[g * H + j] = 0.f;
    g_pool[g * H + j + 32] = 0.f;
    if (g == 0) {
        for (int t = j; t < 3 * H; t += 32) { g_sum[t] = 0.f; g_sumsq[t] = 0.f; }
    }
    __syncwarp();
    float h = l1b[j];
    #pragma unroll
    for (int k = 0; k < H; k++) h = fmaf(p[k], l1w[j * H + k], h);
    h = fmaxf(h, 0.f);
    float v = h * l2w[j];
    #pragma unroll
    for (int o = 16; o; o >>= 1) v += __shfl_xor_sync(0xffffffffu, v, o);
    if (j == 0) out[g] = v + l2b[0];
}

// ------------------------- host launcher -------------------------
extern "C" void kernel_launch(void* const* d_in, const int* in_sizes, int n_in,
                              void* d_out, int out_size) {
    const float* x     = (const float*)d_in[0];
    const int*   ei    = (const int*)d_in[1];     // int32 on device (JAX x64 disabled)
    const int*   batch = (const int*)d_in[2];
    const float* W0  = (const float*)d_in[3];
    const float* b0  = (const float*)d_in[4];
    const float* gm0 = (const float*)d_in[5];
    const float* be0 = (const float*)d_in[6];
    const float* W1  = (const float*)d_in[7];
    const float* b1  = (const float*)d_in[8];
    const float* gm1 = (const float*)d_in[9];
    const float* be1 = (const float*)d_in[10];
    const float* W2  = (const float*)d_in[11];
    const float* b2  = (const float*)d_in[12];
    const float* gm2 = (const float*)d_in[13];
    const float* be2 = (const float*)d_in[14];
    const float* l1w = (const float*)d_in[15];
    const float* l1b = (const float*)d_in[16];
    const float* l2w = (const float*)d_in[17];
    const float* l2b = (const float*)d_in[18];

    int n = in_sizes[0] / 128;     // nodes
    int e = in_sizes[1] / 2;       // edges
    int G = out_size;              // graphs (64)

    int nb = (n + 1023) / 1024;
    int gemm_grid = (n + 63) / 64;
    float fn = (float)n;

    // CSR build; gemm0 at launch #4 so ncu captures it
    hist_kernel<<<(e + 255) / 256, 256>>>(ei, e);                                        // 1
    scanA_kernel<<<nb, 1024>>>(n);                                                       // 2
    scanC_kernel<<<nb, 1024>>>(n, e, nb);                                                // 3
    gemm_kernel<128, false, true><<<gemm_grid, 256>>>(x, W0, nullptr, nullptr, n, 0, fn); // 4
    fill_csr_kernel<<<(e + 255) / 256, 256>>>(ei, e);                                    // 5

    agg_kernel<<<1024, 256>>>(b0, n, 0);                                                 // 6
    gemm_kernel<64, true, false><<<gemm_grid, 256>>>(nullptr, W1, gm0, be0, n, 0, fn);   // 7
    agg_kernel<<<1024, 256>>>(b1, n, 1);                                                 // 8
    gemm_kernel<64, true, false><<<gemm_grid, 256>>>(nullptr, W2, gm1, be1, n, 1, fn);   // 9
    agg_kernel<<<1024, 256>>>(b2, n, 2);                                                 // 10

    pool_kernel<<<G * 8, 256>>>(batch, gm2, be2, n, fn);                                 // 11
    mlp_kernel<<<G, 32>>>(l1w, l1b, l2w, l2b, (float*)d_out);                            // 12
}

// round 10
// speedup vs baseline: 1.1444x; 1.0504x over previous
#include <cuda_runtime.h>
#include <cuda_bf16.h>
#include <cstdint>

#define MAXN 50000
#define MAXE 800000
#define H 64
#define HC 16   // H/4 float4 chunks
#define EPS 1e-5f

// ------------------------- device scratch (no allocs allowed) -------------------------
// Zero-state invariant: g_degcnt, g_pool, g_sum, g_sumsq are zero at entry of every
// kernel_launch call (zero-initialized at module load; each replay restores them).
__device__ __align__(256) float g_bufA[MAXN * H];   // layer output y (agg result)
__device__ __align__(256) float g_bufB[MAXN * H];   // hs = (act @ W^T) * dinv
__device__ int   g_degcnt[MAXN];
__device__ int   g_rowptr[MAXN + 1];
__device__ int   g_cursor[MAXN];
__device__ int   g_csrsrc[MAXE];
__device__ float g_dinv[MAXN];
__device__ float g_sum[3 * H];     // per-layer BN stats
__device__ float g_sumsq[3 * H];
__device__ float g_pool[64 * H];
__device__ int   g_bsum[64];

// ------------------------- CSR build -------------------------
__global__ void hist_kernel(const int* __restrict__ ei, int e) {
    int i = blockIdx.x * blockDim.x + threadIdx.x;
    int stride = gridDim.x * blockDim.x;
    for (int t = i; t < e; t += stride) {
        int dst = ei[e + t];
        atomicAdd(&g_degcnt[dst], 1);
    }
}

__device__ __forceinline__ int block_incl_scan(int v, int tid) {
    __shared__ int ws[32];
    int lane = tid & 31, w = tid >> 5;
    #pragma unroll
    for (int o = 1; o < 32; o <<= 1) {
        int t = __shfl_up_sync(0xffffffffu, v, o);
        if (lane >= o) v += t;
    }
    if (lane == 31) ws[w] = v;
    __syncthreads();
    if (w == 0) {
        int s = ws[lane];
        #pragma unroll
        for (int o = 1; o < 32; o <<= 1) {
            int t = __shfl_up_sync(0xffffffffu, s, o);
            if (lane >= o) s += t;
        }
        ws[lane] = s;
    }
    __syncthreads();
    return v + (w > 0 ? ws[w - 1] : 0);
}

__global__ void scanA_kernel(int n) {
    int tid = threadIdx.x;
    int gid = blockIdx.x * 1024 + tid;
    int v = (gid < n) ? g_degcnt[gid] : 0;
    int incl = block_incl_scan(v, tid);
    if (gid < n) g_rowptr[gid] = incl - v;
    if (tid == 1023) g_bsum[blockIdx.x] = incl;
}

// scanC: adds block offsets, writes rowptr/cursor/dinv, restores g_degcnt to zero.
__global__ void scanC_kernel(int n, int e, int nb) {
    __shared__ int part[2];
    __shared__ int s_off;
    int tid = threadIdx.x;
    if (tid < 64) {
        int v = (tid < blockIdx.x && tid < nb) ? g_bsum[tid] : 0;
        #pragma unroll
        for (int o = 16; o; o >>= 1) v += __shfl_xor_sync(0xffffffffu, v, o);
        if ((tid & 31) == 0) part[tid >> 5] = v;
    }
    __syncthreads();
    if (tid == 0) s_off = part[0] + part[1];
    __syncthreads();
    int off = s_off;

    int gid = blockIdx.x * 1024 + tid;
    if (gid < n) {
        int d = g_degcnt[gid];
        int r = g_rowptr[gid] + off;
        g_rowptr[gid] = r;
        g_cursor[gid] = r;
        g_dinv[gid] = rsqrtf((float)d + 1.0f);
        g_degcnt[gid] = 0;
    }
    if (gid == 0) g_rowptr[n] = e;
}

__global__ void fill_csr_kernel(const int* __restrict__ ei, int e) {
    int i = blockIdx.x * blockDim.x + threadIdx.x;
    int stride = gridDim.x * blockDim.x;
    for (int t = i; t < e; t += stride) {
        int s = ei[t];
        int d = ei[e + t];
        int pos = atomicAdd(&g_cursor[d], 1);
        g_csrsrc[pos] = s;
    }
}

// ------------------------- GEMM: hs = (act @ W^T) * dinv -------------------------
// Register-tiled, shuffle-free. Block = 256 threads = 128 rows x 64 cols tile;
// each thread computes 8x4. A staged TRANSPOSED in smem (a_sm[k][row]), W as
// w_sm[k][col], in 32-wide K chunks. Inner loop per k: 3 LDS.128 + 32 FFMA.
// BN+ReLU folded into the A-stage; dinv at store.
#define KT 32           // K chunk
#define ASTR 132        // a_sm row stride (floats)
#define WSTR 68         // w_sm row stride
template <int K, bool BN, bool FROMX>
__global__ void __launch_bounds__(256) gemm_kernel(const float* __restrict__ in,
                                                   const float* __restrict__ W,
                                                   const float* __restrict__ gamma,
                                                   const float* __restrict__ beta,
                                                   int n, int layer, float fn) {
    __shared__ float a_sm[KT * ASTR];
    __shared__ float w_sm[KT * WSTR];
    __shared__ float sScale[H], sShift[H];

    int tid = threadIdx.x;
    int row0 = blockIdx.x * 128;

    if (BN) {
        if (tid < H) {
            float m = g_sum[layer * H + tid] / fn;
            float var = g_sumsq[layer * H + tid] / fn - m * m;
            float inv = rsqrtf(var + EPS);
            float sc = inv * gamma[tid];
            sScale[tid] = sc;
            sShift[tid] = beta[tid] - m * sc;
        }
        __syncthreads();
    }

    const float* src = FROMX ? in : g_bufA;

    int tx = tid & 15;          // output cols tx*4 .. tx*4+3
    int ty = tid >> 4;          // output rows ty*8 .. ty*8+7

    float acc[8][4];
    #pragma unroll
    for (int r = 0; r < 8; r++)
        #pragma unroll
        for (int c = 0; c < 4; c++) acc[r][c] = 0.f;

    #pragma unroll
    for (int kt = 0; kt < K; kt += KT) {
        // stage W chunk: 64 cols x 32 k = 512 float4, 2 per thread
        #pragma unroll
        for (int it = 0; it < 2; it++) {
            int idx = it * 256 + tid;
            int o = idx & 63;
            int kc = (idx >> 6) << 2;            // 0..28
            float4 wv = *(const float4*)&W[o * K + kt + kc];
            w_sm[(kc + 0) * WSTR + o] = wv.x;
            w_sm[(kc + 1) * WSTR + o] = wv.y;
            w_sm[(kc + 2) * WSTR + o] = wv.z;
            w_sm[(kc + 3) * WSTR + o] = wv.w;
        }
        // stage A chunk transposed: 128 rows x 32 k = 1024 float4, 4 per thread
        #pragma unroll
        for (int it = 0; it < 4; it++) {
            int idx = it * 256 + tid;
            int row = idx & 127;
            int kc = (idx >> 7) << 2;            // 0..28
            int rg = row0 + row;
            float4 av = make_float4(0.f, 0.f, 0.f, 0.f);
            if (rg < n) {
                av = *(const float4*)&src[(size_t)rg * K + kt + kc];
                if (BN) {
                    float4 sc4 = *(const float4*)&sScale[kt + kc];
                    float4 sh4 = *(const float4*)&sShift[kt + kc];
                    av.x = fmaxf(fmaf(av.x, sc4.x, sh4.x), 0.f);
                    av.y = fmaxf(fmaf(av.y, sc4.y, sh4.y), 0.f);
                    av.z = fmaxf(fmaf(av.z, sc4.z, sh4.z), 0.f);
                    av.w = fmaxf(fmaf(av.w, sc4.w, sh4.w), 0.f);
                }
            }
            a_sm[(kc + 0) * ASTR + row] = av.x;
            a_sm[(kc + 1) * ASTR + row] = av.y;
            a_sm[(kc + 2) * ASTR + row] = av.z;
            a_sm[(kc + 3) * ASTR + row] = av.w;
        }
        __syncthreads();

        #pragma unroll
        for (int k = 0; k < KT; k++) {
            float4 a0 = *(const float4*)&a_sm[k * ASTR + ty * 8];
            float4 a1 = *(const float4*)&a_sm[k * ASTR + ty * 8 + 4];
            float4 b4 = *(const float4*)&w_sm[k * WSTR + tx * 4];
            float ar[8] = {a0.x, a0.y, a0.z, a0.w, a1.x, a1.y, a1.z, a1.w};
            float br[4] = {b4.x, b4.y, b4.z, b4.w};
            #pragma unroll
            for (int r = 0; r < 8; r++)
                #pragma unroll
                for (int c = 0; c < 4; c++)
                    acc[r][c] = fmaf(ar[r], br[c], acc[r][c]);
        }
        __syncthreads();
    }

    #pragma unroll
    for (int r = 0; r < 8; r++) {
        int rg = row0 + ty * 8 + r;
        if (rg < n) {
            float dv = g_dinv[rg];
            float4 o4 = make_float4(acc[r][0] * dv, acc[r][1] * dv,
                                    acc[r][2] * dv, acc[r][3] * dv);
            *(float4*)&g_bufB[(size_t)rg * H + tx * 4] = o4;
        }
    }
}

// ------------------------- Aggregation: y = dinv*(sum_nbr hs + hs_self) + bias ------------
// Proven 2-stream structure + 2x unrolled edge loop (two independent accumulators
// per stream -> 4 outstanding gathers per warp). Warp per node; 16 lanes x float4.
__global__ void __launch_bounds__(256) agg_kernel(const float* __restrict__ bias,
                                                  int n, int layer) {
    int tid = threadIdx.x;
    int gw = (blockIdx.x * blockDim.x + tid) >> 5;
    int nw = (gridDim.x * blockDim.x) >> 5;
    int lane = tid & 31, half = lane >> 4, q = lane & 15;

    const float4* hs4 = (const float4*)g_bufB;
    float4* out4 = (float4*)g_bufA;

    float4 s1 = make_float4(0, 0, 0, 0);
    float4 s2 = make_float4(0, 0, 0, 0);
    float4 b4 = make_float4(bias[q * 4], bias[q * 4 + 1], bias[q * 4 + 2], bias[q * 4 + 3]);

    for (int node = gw; node < n; node += nw) {
        int rs = g_rowptr[node];
        int re = g_rowptr[node + 1];
        float4 acc, accB = make_float4(0, 0, 0, 0);
        if (half == 0) acc = hs4[(size_t)node * HC + q];   // self-loop term
        else           acc = make_float4(0, 0, 0, 0);

        int e2 = rs + half;
        for (; e2 + 2 < re; e2 += 4) {
            int i1 = g_csrsrc[e2];
            int i2 = g_csrsrc[e2 + 2];
            float4 v1 = hs4[(size_t)i1 * HC + q];
            float4 v2 = hs4[(size_t)i2 * HC + q];
            acc.x += v1.x; acc.y += v1.y; acc.z += v1.z; acc.w += v1.w;
            accB.x += v2.x; accB.y += v2.y; accB.z += v2.z; accB.w += v2.w;
        }
        if (e2 < re) {
            int i1 = g_csrsrc[e2];
            float4 v1 = hs4[(size_t)i1 * HC + q];
            acc.x += v1.x; acc.y += v1.y; acc.z += v1.z; acc.w += v1.w;
        }
        acc.x += accB.x; acc.y += accB.y; acc.z += accB.z; acc.w += accB.w;

        acc.x += __shfl_xor_sync(0xffffffffu, acc.x, 16);
        acc.y += __shfl_xor_sync(0xffffffffu, acc.y, 16);
        acc.z += __shfl_xor_sync(0xffffffffu, acc.z, 16);
        acc.w += __shfl_xor_sync(0xffffffffu, acc.w, 16);
        if (half == 0) {
            float dv = g_dinv[node];
            float4 y;
            y.x = fmaf(acc.x, dv, b4.x);
            y.y = fmaf(acc.y, dv, b4.y);
            y.z = fmaf(acc.z, dv, b4.z);
            y.w = fmaf(acc.w, dv, b4.w);
            out4[(size_t)node * HC + q] = y;
            s1.x += y.x; s1.y += y.y; s1.z += y.z; s1.w += y.w;
            s2.x += y.x * y.x; s2.y += y.y * y.y; s2.z += y.z * y.z; s2.w += y.w * y.w;
        }
    }

    __shared__ float ssum[H], ssq[H];
    if (tid < H) { ssum[tid] = 0.f; ssq[tid] = 0.f; }
    __syncthreads();
    if (half == 0) {
        int c0 = q * 4;
        atomicAdd(&ssum[c0 + 0], s1.x); atomicAdd(&ssum[c0 + 1], s1.y);
        atomicAdd(&ssum[c0 + 2], s1.z); atomicAdd(&ssum[c0 + 3], s1.w);
        atomicAdd(&ssq[c0 + 0], s2.x);  atomicAdd(&ssq[c0 + 1], s2.y);
        atomicAdd(&ssq[c0 + 2], s2.z);  atomicAdd(&ssq[c0 + 3], s2.w);
    }
    __syncthreads();
    if (tid < H) {
        atomicAdd(&g_sum[layer * H + tid], ssum[tid]);
        atomicAdd(&g_sumsq[layer * H + tid], ssq[tid]);
    }
}

// ------------------------- pooling: segment mean over sorted batch -------------------------
__global__ void __launch_bounds__(256) pool_kernel(const int* __restrict__ batch,
                                                   const float* __restrict__ gamma,
                                                   const float* __restrict__ beta,
                                                   int n, float fn) {
    __shared__ float sScale[H], sShift[H];
    int tid = threadIdx.x;
    if (tid < H) {
        float m = g_sum[2 * H + tid] / fn;
        float var = g_sumsq[2 * H + tid] / fn - m * m;
        float inv = rsqrtf(var + EPS);
        float sc = inv * gamma[tid];
        sScale[tid] = sc;
        sShift[tid] = beta[tid] - m * sc;
    }
    __syncthreads();

    int g = blockIdx.x >> 3, sub = blockIdx.x & 7;
    int start, end;
    {
        int key = g;
        int lo = 0, hi = n;
        while (lo < hi) { int mid = (lo + hi) >> 1; if (batch[mid] < key) lo = mid + 1; else hi = mid; }
        start = lo;
        key = g + 1;
        lo = 0; hi = n;
        while (lo < hi) { int mid = (lo + hi) >> 1; if (batch[mid] < key) lo = mid + 1; else hi = mid; }
        end = lo;
    }
    int c = tid & 63;
    int rr = tid >> 6;  // 0..3
    float sc = sScale[c], sh = sShift[c];
    float cnt = fmaxf((float)(end - start), 1.f);
    float s = 0.f;
    for (int row = start + sub * 4 + rr; row < end; row += 32)
        s += fmaxf(fmaf(g_bufA[(size_t)row * H + c], sc, sh), 0.f);

    __shared__ float sm[256];
    sm[tid] = s;
    __syncthreads();
    if (tid < 128) sm[tid] += sm[tid + 128];
    __syncthreads();
    if (tid < 64) atomicAdd(&g_pool[g * H + tid], (sm[tid] + sm[tid + 64]) / cnt);
}

// ------------------------- final MLP (also restores zero invariants) ----------------------
__global__ void mlp_kernel(const float* __restrict__ l1w, const float* __restrict__ l1b,
                           const float* __restrict__ l2w, const float* __restrict__ l2b,
                           float* __restrict__ out) {
    int g = blockIdx.x, j = threadIdx.x;  // 32 threads
    __shared__ float p[H];
    p[j]      = g_pool[g * H + j];
    p[j + 32] = g_pool[g * H + j + 32];
    g_pool[g * H + j] = 0.f;
    g_pool[g * H + j + 32] = 0.f;
    if (g == 0) {
        for (int t = j; t < 3 * H; t += 32) { g_sum[t] = 0.f; g_sumsq[t] = 0.f; }
    }
    __syncwarp();
    float h = l1b[j];
    #pragma unroll
    for (int k = 0; k < H; k++) h = fmaf(p[k], l1w[j * H + k], h);
    h = fmaxf(h, 0.f);
    float v = h * l2w[j];
    #pragma unroll
    for (int o = 16; o; o >>= 1) v += __shfl_xor_sync(0xffffffffu, v, o);
    if (j == 0) out[g] = v + l2b[0];
}

// ------------------------- host launcher -------------------------
extern "C" void kernel_launch(void* const* d_in, const int* in_sizes, int n_in,
                              void* d_out, int out_size) {
    const float* x     = (const float*)d_in[0];
    const int*   ei    = (const int*)d_in[1];     // int32 on device (JAX x64 disabled)
    const int*   batch = (const int*)d_in[2];
    const float* W0  = (const float*)d_in[3];
    const float* b0  = (const float*)d_in[4];
    const float* gm0 = (const float*)d_in[5];
    const float* be0 = (const float*)d_in[6];
    const float* W1  = (const float*)d_in[7];
    const float* b1  = (const float*)d_in[8];
    const float* gm1 = (const float*)d_in[9];
    const float* be1 = (const float*)d_in[10];
    const float* W2  = (const float*)d_in[11];
    const float* b2  = (const float*)d_in[12];
    const float* gm2 = (const float*)d_in[13];
    const float* be2 = (const float*)d_in[14];
    const float* l1w = (const float*)d_in[15];
    const float* l1b = (const float*)d_in[16];
    const float* l2w = (const float*)d_in[17];
    const float* l2b = (const float*)d_in[18];

    int n = in_sizes[0] / 128;     // nodes
    int e = in_sizes[1] / 2;       // edges
    int G = out_size;              // graphs (64)

    int nb = (n + 1023) / 1024;
    int gemm_grid = (n + 127) / 128;
    float fn = (float)n;

    // CSR build; gemm0 at launch #4 so ncu captures it
    hist_kernel<<<(e + 255) / 256, 256>>>(ei, e);                                        // 1
    scanA_kernel<<<nb, 1024>>>(n);                                                       // 2
    scanC_kernel<<<nb, 1024>>>(n, e, nb);                                                // 3
    gemm_kernel<128, false, true><<<gemm_grid, 256>>>(x, W0, nullptr, nullptr, n, 0, fn); // 4
    fill_csr_kernel<<<(e + 255) / 256, 256>>>(ei, e);                                    // 5

    agg_kernel<<<1024, 256>>>(b0, n, 0);                                                 // 6
    gemm_kernel<64, true, false><<<gemm_grid, 256>>>(nullptr, W1, gm0, be0, n, 0, fn);   // 7
    agg_kernel<<<1024, 256>>>(b1, n, 1);                                                 // 8
    gemm_kernel<64, true, false><<<gemm_grid, 256>>>(nullptr, W2, gm1, be1, n, 1, fn);   // 9
    agg_kernel<<<1024, 256>>>(b2, n, 2);                                                 // 10

    pool_kernel<<<G * 8, 256>>>(batch, gm2, be2, n, fn);                                 // 11
    mlp_kernel<<<G, 32>>>(l1w, l1b, l2w, l2b, (float*)d_out);                            // 12
}